// round 1
// baseline (speedup 1.0000x reference)
#include <cuda_runtime.h>
#include <math_constants.h>

// Problem dims (fixed by setup_inputs)
constexpr int NP = 32768;   // 8*4096 points
constexpr int KC = 2048;    // codebook size
constexpr int D  = 128;     // dim
constexpr float TEMP_INV = 1.0f / 0.9f;
constexpr float LEPS = 1e-6f;

// Scratch (allocation-free rule: __device__ globals)
__device__ float g_scores[(size_t)NP * KC];          // 256 MB score matrix
__device__ float g_esq[KC];                          // ||e_k||^2
__device__ float g_part[(size_t)(NP / 32) * KC];     // per-block class-prob partials (8 MB)
__device__ float g_acc[KC];                          // reduced class sums

// ---------------------------------------------------------------------------
// Kernel 1: e_sq
// ---------------------------------------------------------------------------
__global__ void prep_kernel(const float* __restrict__ embed) {
    int k = blockIdx.x * blockDim.x + threadIdx.x;
    if (k < KC) {
        const float4* e = (const float4*)(embed + (size_t)k * D);
        float s = 0.f;
#pragma unroll
        for (int i = 0; i < D / 4; i++) {
            float4 v = e[i];
            s += v.x * v.x + v.y * v.y + v.z * v.z + v.w * v.w;
        }
        g_esq[k] = s;
    }
}

// ---------------------------------------------------------------------------
// Kernel 2: S = 2*X*E^T - e_sq   (fp32 SGEMM, 128x128 tile, 8x8 per thread)
// ---------------------------------------------------------------------------
constexpr int BM = 128, BN = 128, BK = 16, TM = 8, TN = 8;

__global__ __launch_bounds__(256) void gemm_kernel(const float* __restrict__ X,
                                                   const float* __restrict__ E) {
    __shared__ float As[BK][BM];
    __shared__ float Bs[BK][BN];

    const int bm = blockIdx.y * BM;
    const int bn = blockIdx.x * BN;
    const int tid = threadIdx.x;
    const int tx = tid & 15;        // 0..15 -> n
    const int ty = tid >> 4;        // 0..15 -> m

    float acc[TM][TN];
#pragma unroll
    for (int i = 0; i < TM; i++)
#pragma unroll
        for (int j = 0; j < TN; j++) acc[i][j] = 0.f;

    for (int kk = 0; kk < D; kk += BK) {
        // Load A tile (BM x BK), store transposed As[d][m]
#pragma unroll
        for (int l = 0; l < 2; l++) {
            int f = tid + l * 256;          // 0..511 float4s
            int r = f >> 2;                 // row 0..127
            int c4 = (f & 3) * 4;           // depth 0,4,8,12
            float4 v = *(const float4*)(X + (size_t)(bm + r) * D + kk + c4);
            As[c4 + 0][r] = v.x; As[c4 + 1][r] = v.y;
            As[c4 + 2][r] = v.z; As[c4 + 3][r] = v.w;
        }
        // Load B tile (BN x BK), store transposed Bs[d][k]
#pragma unroll
        for (int l = 0; l < 2; l++) {
            int f = tid + l * 256;
            int r = f >> 2;
            int c4 = (f & 3) * 4;
            float4 v = *(const float4*)(E + (size_t)(bn + r) * D + kk + c4);
            Bs[c4 + 0][r] = v.x; Bs[c4 + 1][r] = v.y;
            Bs[c4 + 2][r] = v.z; Bs[c4 + 3][r] = v.w;
        }
        __syncthreads();

#pragma unroll
        for (int dd = 0; dd < BK; dd++) {
            float a[TM], b[TN];
            float4 a0 = *(const float4*)&As[dd][ty * TM];
            float4 a1 = *(const float4*)&As[dd][ty * TM + 4];
            a[0] = a0.x; a[1] = a0.y; a[2] = a0.z; a[3] = a0.w;
            a[4] = a1.x; a[5] = a1.y; a[6] = a1.z; a[7] = a1.w;
            float4 b0 = *(const float4*)&Bs[dd][tx * TN];
            float4 b1 = *(const float4*)&Bs[dd][tx * TN + 4];
            b[0] = b0.x; b[1] = b0.y; b[2] = b0.z; b[3] = b0.w;
            b[4] = b1.x; b[5] = b1.y; b[6] = b1.z; b[7] = b1.w;
#pragma unroll
            for (int i = 0; i < TM; i++)
#pragma unroll
                for (int j = 0; j < TN; j++) acc[i][j] += a[i] * b[j];
        }
        __syncthreads();
    }

    // Epilogue: S = 2*acc - e_sq[k]
    float esq[TN];
#pragma unroll
    for (int j = 0; j < TN; j++) esq[j] = g_esq[bn + tx * TN + j];

#pragma unroll
    for (int i = 0; i < TM; i++) {
        int m = bm + ty * TM + i;
        float* outp = g_scores + (size_t)m * KC + bn + tx * TN;
#pragma unroll
        for (int j4 = 0; j4 < TN; j4 += 4) {
            float4 v;
            v.x = 2.f * acc[i][j4 + 0] - esq[j4 + 0];
            v.y = 2.f * acc[i][j4 + 1] - esq[j4 + 1];
            v.z = 2.f * acc[i][j4 + 2] - esq[j4 + 2];
            v.w = 2.f * acc[i][j4 + 3] - esq[j4 + 3];
            *(float4*)(outp + j4) = v;
        }
    }
}

// ---------------------------------------------------------------------------
// Kernel 3: per-row argmax + softmax + class-prob partials + outputs
// One warp per row; each lane owns 64 elements (16 float4 chunks).
// Block = 128 threads (4 warps), 32 rows per block.
// ---------------------------------------------------------------------------
__global__ __launch_bounds__(128) void row_kernel(const float* __restrict__ embed,
                                                  float* __restrict__ out) {
    __shared__ float cp[4][KC];   // 32 KB per-warp class-prob accumulators
    const int tid = threadIdx.x;
    const int warp = tid >> 5, lane = tid & 31;

    for (int i = tid; i < 4 * KC; i += 128) (&cp[0][0])[i] = 0.f;
    __syncthreads();

    const int row0 = blockIdx.x * 32;
    float* cpw = cp[warp];

    for (int it = 0; it < 8; it++) {
        const int row = row0 + warp * 8 + it;
        const float* S = g_scores + (size_t)row * KC;

        float v[64];
        float m = -CUDART_INF_F;
        int mi = 0;
#pragma unroll
        for (int j = 0; j < 16; j++) {
            const int kbase = j * 128 + lane * 4;
            float4 q = *(const float4*)(S + kbase);
            v[4 * j + 0] = q.x; v[4 * j + 1] = q.y;
            v[4 * j + 2] = q.z; v[4 * j + 3] = q.w;
            if (q.x > m) { m = q.x; mi = kbase; }
            if (q.y > m) { m = q.y; mi = kbase + 1; }
            if (q.z > m) { m = q.z; mi = kbase + 2; }
            if (q.w > m) { m = q.w; mi = kbase + 3; }
        }
        // warp argmax (ties -> lowest index, matching jnp.argmax)
#pragma unroll
        for (int off = 16; off > 0; off >>= 1) {
            float om = __shfl_xor_sync(0xffffffffu, m, off);
            int oi = __shfl_xor_sync(0xffffffffu, mi, off);
            if (om > m || (om == m && oi < mi)) { m = om; mi = oi; }
        }

        // exp((S - max)/T) and sum (x_sq cancels by shift invariance)
        float s = 0.f;
#pragma unroll
        for (int j = 0; j < 64; j++) {
            float e = __expf((v[j] - m) * TEMP_INV);
            v[j] = e;
            s += e;
        }
#pragma unroll
        for (int off = 16; off > 0; off >>= 1)
            s += __shfl_xor_sync(0xffffffffu, s, off);
        const float inv = 1.f / s;

        // accumulate p into this warp's lane-private smem slots (race-free)
#pragma unroll
        for (int j = 0; j < 16; j++) {
            float4* p = (float4*)(cpw + j * 128 + lane * 4);
            float4 c = *p;
            c.x += v[4 * j + 0] * inv; c.y += v[4 * j + 1] * inv;
            c.z += v[4 * j + 2] * inv; c.w += v[4 * j + 3] * inv;
            *p = c;
        }

        // outputs: quantize (gather codebook row) + embed_ind
        float4 q = *(const float4*)(embed + (size_t)mi * D + lane * 4);
        *(float4*)(out + (size_t)row * D + lane * 4) = q;
        if (lane == 0) out[(size_t)NP * D + row] = (float)mi;
    }

    __syncthreads();
    // deterministic per-block partial (no atomics)
    for (int i = tid; i < KC; i += 128)
        g_part[(size_t)blockIdx.x * KC + i] =
            cp[0][i] + cp[1][i] + cp[2][i] + cp[3][i];
}

// ---------------------------------------------------------------------------
// Kernel 4: reduce partials -> class sums (deterministic)
// ---------------------------------------------------------------------------
__global__ __launch_bounds__(256) void reduce_kernel() {
    int k = blockIdx.x * blockDim.x + threadIdx.x;   // 2048 threads total
    if (k < KC) {
        float s0 = 0.f, s1 = 0.f, s2 = 0.f, s3 = 0.f;
        const int NB = NP / 32;  // 1024 partial blocks
        for (int b = 0; b < NB; b += 4) {
            s0 += g_part[(size_t)(b + 0) * KC + k];
            s1 += g_part[(size_t)(b + 1) * KC + k];
            s2 += g_part[(size_t)(b + 2) * KC + k];
            s3 += g_part[(size_t)(b + 3) * KC + k];
        }
        g_acc[k] = (s0 + s1) + (s2 + s3);
    }
}

// ---------------------------------------------------------------------------
// Kernel 5: diversity loss
// ---------------------------------------------------------------------------
__global__ __launch_bounds__(256) void loss_kernel(float* __restrict__ out) {
    __shared__ float red[8];
    const int tid = threadIdx.x;
    float t = 0.f;
    for (int k = tid; k < KC; k += 256) {
        float p = g_acc[k] * (1.0f / (float)NP);
        t += p * logf(p + LEPS);
    }
#pragma unroll
    for (int off = 16; off > 0; off >>= 1)
        t += __shfl_xor_sync(0xffffffffu, t, off);
    if ((tid & 31) == 0) red[tid >> 5] = t;
    __syncthreads();
    if (tid < 8) {
        t = red[tid];
#pragma unroll
        for (int off = 4; off > 0; off >>= 1)
            t += __shfl_xor_sync(0x000000ffu, t, off);
        if (tid == 0) out[(size_t)NP * D + NP] = t;
    }
}

// ---------------------------------------------------------------------------
extern "C" void kernel_launch(void* const* d_in, const int* in_sizes, int n_in,
                              void* d_out, int out_size) {
    const float* x = (const float*)d_in[0];   // [8,4096,128]
    const float* e = (const float*)d_in[1];   // [2048,128]
    float* out = (float*)d_out;               // [quantize | embed_ind | loss]

    prep_kernel<<<(KC + 255) / 256, 256>>>(e);
    dim3 g(KC / BN, NP / BM);                 // (16, 256)
    gemm_kernel<<<g, 256>>>(x, e);
    row_kernel<<<NP / 32, 128>>>(e, out);
    reduce_kernel<<<KC / 256, 256>>>();
    loss_kernel<<<1, 256>>>(out);
}

// round 4
// speedup vs baseline: 1.0002x; 1.0002x over previous
#include <cuda_runtime.h>
#include <cuda_bf16.h>
#include <math_constants.h>
#include <cstdint>

// Problem dims (fixed by setup_inputs)
constexpr int NP = 32768;   // 8*4096 points
constexpr int KC = 2048;    // codebook size
constexpr int D  = 128;     // dim
constexpr float TEMP_INV = 1.0f / 0.9f;
constexpr float LEPS = 1e-6f;

// Scratch (__device__ globals; no allocation allowed)
__device__ float g_scores[(size_t)NP * KC];            // 256 MB score matrix
__device__ float g_esq[KC];                            // ||e_k||^2
__device__ __nv_bfloat16 g_Xs[(size_t)NP * 384];       // 3-way bf16 split of x
__device__ __nv_bfloat16 g_Es[(size_t)KC * 384];       // 3-way bf16 split of embed
__device__ float g_part[(size_t)(NP / 32) * KC];       // per-block class-prob partials
__device__ float g_part2[16 * KC];                     // stage-1 reduced partials
__device__ float g_acc[KC];                            // class sums

// ---------------------------------------------------------------------------
__device__ __forceinline__ uint32_t smem_u32(const void* p) {
    uint32_t a;
    asm("{ .reg .u64 t; cvta.to.shared.u64 t, %1; cvt.u32.u64 %0, t; }" : "=r"(a) : "l"(p));
    return a;
}
__device__ __forceinline__ uint32_t sw128(uint32_t off) { return off ^ ((off >> 3) & 0x70); }

__device__ __forceinline__ void cp_async16(uint32_t saddr, const void* gaddr) {
    asm volatile("cp.async.cg.shared.global [%0], [%1], 16;" :: "r"(saddr), "l"(gaddr));
}
#define CP_COMMIT() asm volatile("cp.async.commit_group;" ::: "memory")
#define CP_WAIT(n)  asm volatile("cp.async.wait_group %0;" :: "n"(n) : "memory")

__device__ __forceinline__ void ldm_a(uint32_t* a, uint32_t addr) {
    asm volatile("ldmatrix.sync.aligned.m8n8.x4.shared.b16 {%0,%1,%2,%3}, [%4];"
                 : "=r"(a[0]), "=r"(a[1]), "=r"(a[2]), "=r"(a[3]) : "r"(addr));
}
// B stored [n][k] (k contiguous) == col-major (k,n): NON-trans ldmatrix gives
// the correct m16n8k16 B fragment (thread t -> B[k=2*(t&3)+i][n=t>>2]).
__device__ __forceinline__ void ldm_b(uint32_t* b, uint32_t addr) {
    asm volatile("ldmatrix.sync.aligned.m8n8.x2.shared.b16 {%0,%1}, [%2];"
                 : "=r"(b[0]), "=r"(b[1]) : "r"(addr));
}
__device__ __forceinline__ void mma_bf16(float* c, const uint32_t* a, const uint32_t* b) {
    asm volatile("mma.sync.aligned.m16n8k16.row.col.f32.bf16.bf16.f32 "
                 "{%0,%1,%2,%3}, {%4,%5,%6,%7}, {%8,%9}, {%0,%1,%2,%3};"
                 : "+f"(c[0]), "+f"(c[1]), "+f"(c[2]), "+f"(c[3])
                 : "r"(a[0]), "r"(a[1]), "r"(a[2]), "r"(a[3]), "r"(b[0]), "r"(b[1]));
}

// ---------------------------------------------------------------------------
// Kernel 0: 3-way bf16 split of x and embed
// ---------------------------------------------------------------------------
__global__ __launch_bounds__(256) void split_kernel(const float* __restrict__ x,
                                                    const float* __restrict__ e) {
    int i = blockIdx.x * 256 + threadIdx.x;
    float v; __nv_bfloat16* dst; int c;
    if (i < NP * D) {
        v = x[i]; c = i & (D - 1);
        dst = g_Xs + (size_t)(i >> 7) * 384;
    } else {
        int j = i - NP * D;
        if (j >= KC * D) return;
        v = e[j]; c = j & (D - 1);
        dst = g_Es + (size_t)(j >> 7) * 384;
    }
    __nv_bfloat16 b0 = __float2bfloat16(v);
    float r1 = v - __bfloat162float(b0);
    __nv_bfloat16 b1 = __float2bfloat16(r1);
    float r2 = r1 - __bfloat162float(b1);
    __nv_bfloat16 b2 = __float2bfloat16(r2);
    dst[c] = b0; dst[128 + c] = b1; dst[256 + c] = b2;
}

// ---------------------------------------------------------------------------
// Kernel 1: e_sq
// ---------------------------------------------------------------------------
__global__ void prep_kernel(const float* __restrict__ embed) {
    int k = blockIdx.x * blockDim.x + threadIdx.x;
    if (k < KC) {
        const float4* e = (const float4*)(embed + (size_t)k * D);
        float s = 0.f;
#pragma unroll
        for (int i = 0; i < D / 4; i++) {
            float4 v = e[i];
            s += v.x * v.x + v.y * v.y + v.z * v.z + v.w * v.w;
        }
        g_esq[k] = s;
    }
}

// ---------------------------------------------------------------------------
// Kernel 2: mma.sync bf16 GEMM  S = 2*(X*E^T via 6 split-products) - e_sq
// Block 256 thr, tile M128 x N128, 12 K-chunks of 64 (virtual K=768).
// ---------------------------------------------------------------------------
constexpr int STG_SZ = 128 * 128;                 // 16 KB per operand stage
constexpr int GEMM_SMEM = 128 * 129 * 4;          // 66048 B (>= 4*STG_SZ)

__constant__ int c_PA[6] = {0, 0, 1, 0, 1, 2};
__constant__ int c_PB[6] = {0, 1, 0, 2, 1, 0};

__global__ __launch_bounds__(256, 2) void gemm_kernel() {
    extern __shared__ char smem[];
    const uint32_t sb = smem_u32(smem);
    const int tid = threadIdx.x, wid = tid >> 5, lane = tid & 31;
    const int warp_m = wid & 3, warp_n = wid >> 2;
    const int bm = blockIdx.y * 128, bn = blockIdx.x * 128;

    float acc[2][8][4];
#pragma unroll
    for (int mt = 0; mt < 2; mt++)
#pragma unroll
        for (int nt = 0; nt < 8; nt++)
#pragma unroll
            for (int q = 0; q < 4; q++) acc[mt][nt][q] = 0.f;

    // per-thread load coords: 4 x 16B for A, 4 x 16B for B per chunk
    const int lr = tid >> 1;                 // rows 0..127 (2 threads/row)
    const int ls0 = (tid & 1) * 4;           // 16B segment 0..7 (4 each)

    // ldmatrix per-lane address components
    const int arow = warp_m * 32 + (lane & 7) + ((lane >> 3) & 1) * 8;
    const int acol = ((lane >> 4) & 1) * 16;
    const int brow = warp_n * 64 + (lane & 7);
    const int bcol = ((lane >> 3) & 1) * 16;

    auto issue_chunk = [&](int c, int stage) {
        const int p = c >> 1, h = c & 1;
        const int aoff = c_PA[p] * 128 + h * 64;
        const int boff = c_PB[p] * 128 + h * 64;
        const uint32_t sa = sb + stage * 2 * STG_SZ;
        const uint32_t sbB = sa + STG_SZ;
        const __nv_bfloat16* ga = g_Xs + (size_t)(bm + lr) * 384 + aoff;
        const __nv_bfloat16* gb = g_Es + (size_t)(bn + lr) * 384 + boff;
#pragma unroll
        for (int s = 0; s < 4; s++) {
            cp_async16(sa + sw128((uint32_t)lr * 128 + (ls0 + s) * 16), ga + (ls0 + s) * 8);
            cp_async16(sbB + sw128((uint32_t)lr * 128 + (ls0 + s) * 16), gb + (ls0 + s) * 8);
        }
        CP_COMMIT();
    };

    issue_chunk(0, 0);

#pragma unroll 1
    for (int c = 0; c < 12; c++) {
        const int stage = c & 1;
        if (c < 11) {
            issue_chunk(c + 1, stage ^ 1);
            CP_WAIT(1);
        } else {
            CP_WAIT(0);
        }
        __syncthreads();

        const uint32_t sa = sb + stage * 2 * STG_SZ;
        const uint32_t sbB = sa + STG_SZ;
#pragma unroll
        for (int ks = 0; ks < 4; ks++) {
            uint32_t a[2][4];
#pragma unroll
            for (int mt = 0; mt < 2; mt++)
                ldm_a(a[mt], sa + sw128((uint32_t)(arow + mt * 16) * 128 + ks * 32 + acol));
#pragma unroll
            for (int nt = 0; nt < 8; nt++) {
                uint32_t b[2];
                ldm_b(b, sbB + sw128((uint32_t)(brow + nt * 8) * 128 + ks * 32 + bcol));
                mma_bf16(acc[0][nt], a[0], b);
                mma_bf16(acc[1][nt], a[1], b);
            }
        }
        __syncthreads();
    }

    // Epilogue: accum -> padded smem tile -> coalesced (2*s - esq) stores
    float* tile = (float*)smem;
#pragma unroll
    for (int mt = 0; mt < 2; mt++) {
        const int r = warp_m * 32 + mt * 16 + (lane >> 2);
#pragma unroll
        for (int nt = 0; nt < 8; nt++) {
            const int cb = warp_n * 64 + nt * 8 + 2 * (lane & 3);
            tile[r * 129 + cb]           = acc[mt][nt][0];
            tile[r * 129 + cb + 1]       = acc[mt][nt][1];
            tile[(r + 8) * 129 + cb]     = acc[mt][nt][2];
            tile[(r + 8) * 129 + cb + 1] = acc[mt][nt][3];
        }
    }
    __syncthreads();

#pragma unroll
    for (int i = 0; i < 16; i++) {
        const int lin = tid + i * 256;           // 0..4095
        const int row = lin >> 5;
        const int c4 = (lin & 31) * 4;
        const float4 esq = *(const float4*)(g_esq + bn + c4);
        float4 v;
        v.x = 2.f * tile[row * 129 + c4 + 0] - esq.x;
        v.y = 2.f * tile[row * 129 + c4 + 1] - esq.y;
        v.z = 2.f * tile[row * 129 + c4 + 2] - esq.z;
        v.w = 2.f * tile[row * 129 + c4 + 3] - esq.w;
        *(float4*)(g_scores + (size_t)(bm + row) * KC + bn + c4) = v;
    }
}

// ---------------------------------------------------------------------------
// Kernel 3: per-row argmax + softmax + class-prob partials + outputs
// ---------------------------------------------------------------------------
__global__ __launch_bounds__(128) void row_kernel(const float* __restrict__ embed,
                                                  float* __restrict__ out) {
    __shared__ float cp[4][KC];
    const int tid = threadIdx.x;
    const int warp = tid >> 5, lane = tid & 31;

    for (int i = tid; i < 4 * KC; i += 128) (&cp[0][0])[i] = 0.f;
    __syncthreads();

    const int row0 = blockIdx.x * 32;
    float* cpw = cp[warp];

    for (int it = 0; it < 8; it++) {
        const int row = row0 + warp * 8 + it;
        const float* S = g_scores + (size_t)row * KC;

        float v[64];
        float m = -CUDART_INF_F;
        int mi = 0;
#pragma unroll
        for (int j = 0; j < 16; j++) {
            const int kbase = j * 128 + lane * 4;
            float4 q = *(const float4*)(S + kbase);
            v[4 * j + 0] = q.x; v[4 * j + 1] = q.y;
            v[4 * j + 2] = q.z; v[4 * j + 3] = q.w;
            if (q.x > m) { m = q.x; mi = kbase; }
            if (q.y > m) { m = q.y; mi = kbase + 1; }
            if (q.z > m) { m = q.z; mi = kbase + 2; }
            if (q.w > m) { m = q.w; mi = kbase + 3; }
        }
#pragma unroll
        for (int off = 16; off > 0; off >>= 1) {
            float om = __shfl_xor_sync(0xffffffffu, m, off);
            int oi = __shfl_xor_sync(0xffffffffu, mi, off);
            if (om > m || (om == m && oi < mi)) { m = om; mi = oi; }
        }

        float s = 0.f;
#pragma unroll
        for (int j = 0; j < 64; j++) {
            float e = __expf((v[j] - m) * TEMP_INV);
            v[j] = e;
            s += e;
        }
#pragma unroll
        for (int off = 16; off > 0; off >>= 1)
            s += __shfl_xor_sync(0xffffffffu, s, off);
        const float inv = 1.f / s;

#pragma unroll
        for (int j = 0; j < 16; j++) {
            float4* p = (float4*)(cpw + j * 128 + lane * 4);
            float4 c = *p;
            c.x += v[4 * j + 0] * inv; c.y += v[4 * j + 1] * inv;
            c.z += v[4 * j + 2] * inv; c.w += v[4 * j + 3] * inv;
            *p = c;
        }

        float4 q = *(const float4*)(embed + (size_t)mi * D + lane * 4);
        *(float4*)(out + (size_t)row * D + lane * 4) = q;
        if (lane == 0) out[(size_t)NP * D + row] = (float)mi;
    }

    __syncthreads();
    for (int i = tid; i < KC; i += 128)
        g_part[(size_t)blockIdx.x * KC + i] =
            cp[0][i] + cp[1][i] + cp[2][i] + cp[3][i];
}

// ---------------------------------------------------------------------------
// Kernel 4a/4b: two-stage deterministic reduce of partials
// ---------------------------------------------------------------------------
__global__ __launch_bounds__(256) void reduce1_kernel() {
    const int k = blockIdx.x * 256 + threadIdx.x;
    const int b0 = blockIdx.y * 64;
    float s0 = 0.f, s1 = 0.f, s2 = 0.f, s3 = 0.f;
    for (int b = 0; b < 64; b += 4) {
        s0 += g_part[(size_t)(b0 + b + 0) * KC + k];
        s1 += g_part[(size_t)(b0 + b + 1) * KC + k];
        s2 += g_part[(size_t)(b0 + b + 2) * KC + k];
        s3 += g_part[(size_t)(b0 + b + 3) * KC + k];
    }
    g_part2[blockIdx.y * KC + k] = (s0 + s1) + (s2 + s3);
}

__global__ __launch_bounds__(256) void reduce2_kernel() {
    const int k = blockIdx.x * 256 + threadIdx.x;
    float s = 0.f;
#pragma unroll
    for (int b = 0; b < 16; b++) s += g_part2[b * KC + k];
    g_acc[k] = s;
}

// ---------------------------------------------------------------------------
// Kernel 5: diversity loss
// ---------------------------------------------------------------------------
__global__ __launch_bounds__(256) void loss_kernel(float* __restrict__ out) {
    __shared__ float red[8];
    const int tid = threadIdx.x;
    float t = 0.f;
    for (int k = tid; k < KC; k += 256) {
        float p = g_acc[k] * (1.0f / (float)NP);
        t += p * logf(p + LEPS);
    }
#pragma unroll
    for (int off = 16; off > 0; off >>= 1)
        t += __shfl_xor_sync(0xffffffffu, t, off);
    if ((tid & 31) == 0) red[tid >> 5] = t;
    __syncthreads();
    if (tid < 8) {
        t = red[tid];
#pragma unroll
        for (int off = 4; off > 0; off >>= 1)
            t += __shfl_xor_sync(0x000000ffu, t, off);
        if (tid == 0) out[(size_t)NP * D + NP] = t;
    }
}

// ---------------------------------------------------------------------------
extern "C" void kernel_launch(void* const* d_in, const int* in_sizes, int n_in,
                              void* d_out, int out_size) {
    const float* x = (const float*)d_in[0];
    const float* e = (const float*)d_in[1];
    float* out = (float*)d_out;

    cudaFuncSetAttribute(gemm_kernel, cudaFuncAttributeMaxDynamicSharedMemorySize, GEMM_SMEM);

    split_kernel<<<((NP + KC) * D + 255) / 256, 256>>>(x, e);
    prep_kernel<<<(KC + 255) / 256, 256>>>(e);
    gemm_kernel<<<dim3(KC / 128, NP / 128), 256, GEMM_SMEM>>>();
    row_kernel<<<NP / 32, 128>>>(e, out);
    reduce1_kernel<<<dim3(KC / 256, 16), 256>>>();
    reduce2_kernel<<<KC / 256, 256>>>();
    loss_kernel<<<1, 256>>>(out);
}

// round 5
// speedup vs baseline: 1.4974x; 1.4971x over previous
#include <cuda_runtime.h>
#include <cuda_bf16.h>
#include <math_constants.h>
#include <cstdint>

// Problem dims (fixed by setup_inputs)
constexpr int NP = 32768;   // 8*4096 points
constexpr int KC = 2048;    // codebook size
constexpr int D  = 128;     // dim
constexpr float TEMP_INV = 1.0f / 0.9f;
constexpr float LEPS = 1e-6f;
constexpr float RESCUE_THR = 1e-2f;   // approx-score margin for exact rescoring

// Scratch (__device__ globals; no allocation allowed)
__device__ float g_scores[(size_t)NP * KC];            // 256 MB score matrix
__device__ float g_esq[KC];                            // ||e_k||^2
__device__ __nv_bfloat16 g_Xs[(size_t)NP * 256];       // 2-way bf16 split of x
__device__ __nv_bfloat16 g_Es[(size_t)KC * 256];       // 2-way bf16 split of embed
__device__ float g_part[(size_t)(NP / 32) * KC];       // per-block class-prob partials
__device__ float g_part2[16 * KC];                     // stage-1 reduced partials
__device__ float g_acc[KC];                            // class sums

// ---------------------------------------------------------------------------
__device__ __forceinline__ uint32_t smem_u32(const void* p) {
    uint32_t a;
    asm("{ .reg .u64 t; cvta.to.shared.u64 t, %1; cvt.u32.u64 %0, t; }" : "=r"(a) : "l"(p));
    return a;
}
__device__ __forceinline__ uint32_t sw128(uint32_t off) { return off ^ ((off >> 3) & 0x70); }

__device__ __forceinline__ void cp_async16(uint32_t saddr, const void* gaddr) {
    asm volatile("cp.async.cg.shared.global [%0], [%1], 16;" :: "r"(saddr), "l"(gaddr));
}
#define CP_COMMIT() asm volatile("cp.async.commit_group;" ::: "memory")
#define CP_WAIT(n)  asm volatile("cp.async.wait_group %0;" :: "n"(n) : "memory")

__device__ __forceinline__ void ldm_a(uint32_t* a, uint32_t addr) {
    asm volatile("ldmatrix.sync.aligned.m8n8.x4.shared.b16 {%0,%1,%2,%3}, [%4];"
                 : "=r"(a[0]), "=r"(a[1]), "=r"(a[2]), "=r"(a[3]) : "r"(addr));
}
// B stored [n][k] (k contiguous) == col-major (k,n): NON-trans ldmatrix.
__device__ __forceinline__ void ldm_b(uint32_t* b, uint32_t addr) {
    asm volatile("ldmatrix.sync.aligned.m8n8.x2.shared.b16 {%0,%1}, [%2];"
                 : "=r"(b[0]), "=r"(b[1]) : "r"(addr));
}
__device__ __forceinline__ void mma_bf16(float* c, const uint32_t* a, const uint32_t* b) {
    asm volatile("mma.sync.aligned.m16n8k16.row.col.f32.bf16.bf16.f32 "
                 "{%0,%1,%2,%3}, {%4,%5,%6,%7}, {%8,%9}, {%0,%1,%2,%3};"
                 : "+f"(c[0]), "+f"(c[1]), "+f"(c[2]), "+f"(c[3])
                 : "r"(a[0]), "r"(a[1]), "r"(a[2]), "r"(a[3]), "r"(b[0]), "r"(b[1]));
}

// ---------------------------------------------------------------------------
// Kernel 0: 2-way bf16 split of x and embed
// ---------------------------------------------------------------------------
__global__ __launch_bounds__(256) void split_kernel(const float* __restrict__ x,
                                                    const float* __restrict__ e) {
    int i = blockIdx.x * 256 + threadIdx.x;
    float v; __nv_bfloat16* dst; int c;
    if (i < NP * D) {
        v = x[i]; c = i & (D - 1);
        dst = g_Xs + (size_t)(i >> 7) * 256;
    } else {
        int j = i - NP * D;
        if (j >= KC * D) return;
        v = e[j]; c = j & (D - 1);
        dst = g_Es + (size_t)(j >> 7) * 256;
    }
    __nv_bfloat16 b0 = __float2bfloat16(v);
    float r1 = v - __bfloat162float(b0);
    __nv_bfloat16 b1 = __float2bfloat16(r1);
    dst[c] = b0; dst[128 + c] = b1;
}

// ---------------------------------------------------------------------------
// Kernel 1: e_sq
// ---------------------------------------------------------------------------
__global__ void prep_kernel(const float* __restrict__ embed) {
    int k = blockIdx.x * blockDim.x + threadIdx.x;
    if (k < KC) {
        const float4* e = (const float4*)(embed + (size_t)k * D);
        float s = 0.f;
#pragma unroll
        for (int i = 0; i < D / 4; i++) {
            float4 v = e[i];
            s += v.x * v.x + v.y * v.y + v.z * v.z + v.w * v.w;
        }
        g_esq[k] = s;
    }
}

// ---------------------------------------------------------------------------
// Kernel 2: mma.sync bf16 GEMM  S = 2*(X*E^T via 3 split-products) - e_sq
// Block 256 thr, tile M128 x N128, 6 K-chunks of 64 (virtual K=384).
// ---------------------------------------------------------------------------
constexpr int STG_SZ = 128 * 128;                 // 16 KB per operand stage
constexpr int GEMM_SMEM = 128 * 129 * 4;          // 66048 B (>= 4*STG_SZ)

__constant__ int c_PA[3] = {0, 0, 1};
__constant__ int c_PB[3] = {0, 1, 0};

__global__ __launch_bounds__(256, 2) void gemm_kernel() {
    extern __shared__ char smem[];
    const uint32_t sb = smem_u32(smem);
    const int tid = threadIdx.x, wid = tid >> 5, lane = tid & 31;
    const int warp_m = wid & 3, warp_n = wid >> 2;
    const int bm = blockIdx.y * 128, bn = blockIdx.x * 128;

    float acc[2][8][4];
#pragma unroll
    for (int mt = 0; mt < 2; mt++)
#pragma unroll
        for (int nt = 0; nt < 8; nt++)
#pragma unroll
            for (int q = 0; q < 4; q++) acc[mt][nt][q] = 0.f;

    const int lr = tid >> 1;                 // rows 0..127 (2 threads/row)
    const int ls0 = (tid & 1) * 4;           // 16B segment base

    const int arow = warp_m * 32 + (lane & 7) + ((lane >> 3) & 1) * 8;
    const int acol = ((lane >> 4) & 1) * 16;
    const int brow = warp_n * 64 + (lane & 7);
    const int bcol = ((lane >> 3) & 1) * 16;

    auto issue_chunk = [&](int c, int stage) {
        const int p = c >> 1, h = c & 1;
        const int aoff = c_PA[p] * 128 + h * 64;
        const int boff = c_PB[p] * 128 + h * 64;
        const uint32_t sa = sb + stage * 2 * STG_SZ;
        const uint32_t sbB = sa + STG_SZ;
        const __nv_bfloat16* ga = g_Xs + (size_t)(bm + lr) * 256 + aoff;
        const __nv_bfloat16* gb = g_Es + (size_t)(bn + lr) * 256 + boff;
#pragma unroll
        for (int s = 0; s < 4; s++) {
            cp_async16(sa + sw128((uint32_t)lr * 128 + (ls0 + s) * 16), ga + (ls0 + s) * 8);
            cp_async16(sbB + sw128((uint32_t)lr * 128 + (ls0 + s) * 16), gb + (ls0 + s) * 8);
        }
        CP_COMMIT();
    };

    issue_chunk(0, 0);

#pragma unroll 1
    for (int c = 0; c < 6; c++) {
        const int stage = c & 1;
        if (c < 5) {
            issue_chunk(c + 1, stage ^ 1);
            CP_WAIT(1);
        } else {
            CP_WAIT(0);
        }
        __syncthreads();

        const uint32_t sa = sb + stage * 2 * STG_SZ;
        const uint32_t sbB = sa + STG_SZ;
#pragma unroll
        for (int ks = 0; ks < 4; ks++) {
            uint32_t a[2][4];
#pragma unroll
            for (int mt = 0; mt < 2; mt++)
                ldm_a(a[mt], sa + sw128((uint32_t)(arow + mt * 16) * 128 + ks * 32 + acol));
#pragma unroll
            for (int nt = 0; nt < 8; nt++) {
                uint32_t b[2];
                ldm_b(b, sbB + sw128((uint32_t)(brow + nt * 8) * 128 + ks * 32 + bcol));
                mma_bf16(acc[0][nt], a[0], b);
                mma_bf16(acc[1][nt], a[1], b);
            }
        }
        __syncthreads();
    }

    // Epilogue: accum -> padded smem tile -> coalesced (2*s - esq) stores
    float* tile = (float*)smem;
#pragma unroll
    for (int mt = 0; mt < 2; mt++) {
        const int r = warp_m * 32 + mt * 16 + (lane >> 2);
#pragma unroll
        for (int nt = 0; nt < 8; nt++) {
            const int cb = warp_n * 64 + nt * 8 + 2 * (lane & 3);
            tile[r * 129 + cb]           = acc[mt][nt][0];
            tile[r * 129 + cb + 1]       = acc[mt][nt][1];
            tile[(r + 8) * 129 + cb]     = acc[mt][nt][2];
            tile[(r + 8) * 129 + cb + 1] = acc[mt][nt][3];
        }
    }
    __syncthreads();

#pragma unroll
    for (int i = 0; i < 16; i++) {
        const int lin = tid + i * 256;           // 0..4095
        const int row = lin >> 5;
        const int c4 = (lin & 31) * 4;
        const float4 esq = *(const float4*)(g_esq + bn + c4);
        float4 v;
        v.x = 2.f * tile[row * 129 + c4 + 0] - esq.x;
        v.y = 2.f * tile[row * 129 + c4 + 1] - esq.y;
        v.z = 2.f * tile[row * 129 + c4 + 2] - esq.z;
        v.w = 2.f * tile[row * 129 + c4 + 3] - esq.w;
        *(float4*)(g_scores + (size_t)(bm + row) * KC + bn + c4) = v;
    }
}

// ---------------------------------------------------------------------------
// Kernel 3: per-row argmax (+ exact fp32 rescue for near-ties) + softmax +
// class-prob partials + outputs.
// ---------------------------------------------------------------------------
__global__ __launch_bounds__(128) void row_kernel(const float* __restrict__ x,
                                                  const float* __restrict__ embed,
                                                  float* __restrict__ out) {
    __shared__ float cp[4][KC];
    __shared__ int s_cnt[4];
    __shared__ int s_list[4][16];
    const int tid = threadIdx.x;
    const int warp = tid >> 5, lane = tid & 31;

    for (int i = tid; i < 4 * KC; i += 128) (&cp[0][0])[i] = 0.f;
    __syncthreads();

    const int row0 = blockIdx.x * 32;
    float* cpw = cp[warp];

    for (int it = 0; it < 8; it++) {
        const int row = row0 + warp * 8 + it;
        const float* S = g_scores + (size_t)row * KC;

        float v[64];
        float m = -CUDART_INF_F;
        int mi = 0;
#pragma unroll
        for (int j = 0; j < 16; j++) {
            const int kbase = j * 128 + lane * 4;
            float4 q = *(const float4*)(S + kbase);
            v[4 * j + 0] = q.x; v[4 * j + 1] = q.y;
            v[4 * j + 2] = q.z; v[4 * j + 3] = q.w;
            if (q.x > m) { m = q.x; mi = kbase; }
            if (q.y > m) { m = q.y; mi = kbase + 1; }
            if (q.z > m) { m = q.z; mi = kbase + 2; }
            if (q.w > m) { m = q.w; mi = kbase + 3; }
        }
#pragma unroll
        for (int off = 16; off > 0; off >>= 1) {
            float om = __shfl_xor_sync(0xffffffffu, m, off);
            int oi = __shfl_xor_sync(0xffffffffu, mi, off);
            if (om > m || (om == m && oi < mi)) { m = om; mi = oi; }
        }

        // Candidate detection for exact rescue (before v[] is overwritten).
        const float thr = m - RESCUE_THR;
        int cnt = 0;
#pragma unroll
        for (int j = 0; j < 64; j++) cnt += (v[j] > thr) ? 1 : 0;
#pragma unroll
        for (int off = 16; off > 0; off >>= 1)
            cnt += __shfl_xor_sync(0xffffffffu, cnt, off);

        if (cnt > 1) {
            if (lane == 0) s_cnt[warp] = 0;
            __syncwarp();
#pragma unroll
            for (int j = 0; j < 64; j++) {
                if (v[j] > thr) {
                    int pos = atomicAdd(&s_cnt[warp], 1);
                    if (pos < 16)
                        s_list[warp][pos] = (j >> 2) * 128 + lane * 4 + (j & 3);
                }
            }
            __syncwarp();
            const int nc = min(s_cnt[warp], 16);
            const float4 xa = *(const float4*)(x + (size_t)row * D + lane * 4);
            float bv = -CUDART_INF_F; int bi = 0x7fffffff;
            for (int t = 0; t < nc; t++) {
                const int cidx = s_list[warp][t];
                const float4 ea = *(const float4*)(embed + (size_t)cidx * D + lane * 4);
                float d = xa.x * ea.x + xa.y * ea.y + xa.z * ea.z + xa.w * ea.w;
#pragma unroll
                for (int off = 16; off > 0; off >>= 1)
                    d += __shfl_xor_sync(0xffffffffu, d, off);
                const float sc = 2.f * d - g_esq[cidx];
                if (sc > bv || (sc == bv && cidx < bi)) { bv = sc; bi = cidx; }
            }
            mi = bi;
        }

        // softmax (approx scores — fine for the loss)
        float s = 0.f;
#pragma unroll
        for (int j = 0; j < 64; j++) {
            float e = __expf((v[j] - m) * TEMP_INV);
            v[j] = e;
            s += e;
        }
#pragma unroll
        for (int off = 16; off > 0; off >>= 1)
            s += __shfl_xor_sync(0xffffffffu, s, off);
        const float inv = 1.f / s;

#pragma unroll
        for (int j = 0; j < 16; j++) {
            float4* p = (float4*)(cpw + j * 128 + lane * 4);
            float4 c = *p;
            c.x += v[4 * j + 0] * inv; c.y += v[4 * j + 1] * inv;
            c.z += v[4 * j + 2] * inv; c.w += v[4 * j + 3] * inv;
            *p = c;
        }

        float4 q = *(const float4*)(embed + (size_t)mi * D + lane * 4);
        *(float4*)(out + (size_t)row * D + lane * 4) = q;
        if (lane == 0) out[(size_t)NP * D + row] = (float)mi;
    }

    __syncthreads();
    for (int i = tid; i < KC; i += 128)
        g_part[(size_t)blockIdx.x * KC + i] =
            cp[0][i] + cp[1][i] + cp[2][i] + cp[3][i];
}

// ---------------------------------------------------------------------------
// Kernel 4a/4b: two-stage deterministic reduce of partials
// ---------------------------------------------------------------------------
__global__ __launch_bounds__(256) void reduce1_kernel() {
    const int k = blockIdx.x * 256 + threadIdx.x;
    const int b0 = blockIdx.y * 64;
    float s0 = 0.f, s1 = 0.f, s2 = 0.f, s3 = 0.f;
    for (int b = 0; b < 64; b += 4) {
        s0 += g_part[(size_t)(b0 + b + 0) * KC + k];
        s1 += g_part[(size_t)(b0 + b + 1) * KC + k];
        s2 += g_part[(size_t)(b0 + b + 2) * KC + k];
        s3 += g_part[(size_t)(b0 + b + 3) * KC + k];
    }
    g_part2[blockIdx.y * KC + k] = (s0 + s1) + (s2 + s3);
}

__global__ __launch_bounds__(256) void reduce2_kernel() {
    const int k = blockIdx.x * 256 + threadIdx.x;
    float s = 0.f;
#pragma unroll
    for (int b = 0; b < 16; b++) s += g_part2[b * KC + k];
    g_acc[k] = s;
}

// ---------------------------------------------------------------------------
// Kernel 5: diversity loss
// ---------------------------------------------------------------------------
__global__ __launch_bounds__(256) void loss_kernel(float* __restrict__ out) {
    __shared__ float red[8];
    const int tid = threadIdx.x;
    float t = 0.f;
    for (int k = tid; k < KC; k += 256) {
        float p = g_acc[k] * (1.0f / (float)NP);
        t += p * logf(p + LEPS);
    }
#pragma unroll
    for (int off = 16; off > 0; off >>= 1)
        t += __shfl_xor_sync(0xffffffffu, t, off);
    if ((tid & 31) == 0) red[tid >> 5] = t;
    __syncthreads();
    if (tid < 8) {
        t = red[tid];
#pragma unroll
        for (int off = 4; off > 0; off >>= 1)
            t += __shfl_xor_sync(0x000000ffu, t, off);
        if (tid == 0) out[(size_t)NP * D + NP] = t;
    }
}

// ---------------------------------------------------------------------------
extern "C" void kernel_launch(void* const* d_in, const int* in_sizes, int n_in,
                              void* d_out, int out_size) {
    const float* x = (const float*)d_in[0];
    const float* e = (const float*)d_in[1];
    float* out = (float*)d_out;

    cudaFuncSetAttribute(gemm_kernel, cudaFuncAttributeMaxDynamicSharedMemorySize, GEMM_SMEM);

    split_kernel<<<((NP + KC) * D + 255) / 256, 256>>>(x, e);
    prep_kernel<<<(KC + 255) / 256, 256>>>(e);
    gemm_kernel<<<dim3(KC / 128, NP / 128), 256, GEMM_SMEM>>>();
    row_kernel<<<NP / 32, 128>>>(x, e, out);
    reduce1_kernel<<<dim3(KC / 256, 16), 256>>>();
    reduce2_kernel<<<KC / 256, 256>>>();
    loss_kernel<<<1, 256>>>(out);
}